// round 1
// baseline (speedup 1.0000x reference)
#include <cuda_runtime.h>

// ---------------------------------------------------------------------------
// ImprovedAILayerNorm: int8-quantized layernorm with LUT integer sqrt.
// 3-pass structure (global scale_in -> per-row stats + global scale_out ->
// quantized output), float4 I/O, rows held in registers.
// ---------------------------------------------------------------------------

#define THREADS 256
#define MAX_ROWS 32768

// Scratch (allocation-free: __device__ globals)
__device__ int   g_absmax_bits;
__device__ int   g_ymax_bits;
__device__ float g_scale_in;
__device__ float g_scale_out;
__device__ float g_mu[MAX_ROWS];
__device__ float g_inv_std[MAX_ROWS];

// ---------------------------------------------------------------------------
__global__ void k_init() {
    g_absmax_bits = 0;
    g_ymax_bits   = 0;
}

// ---------------------------------------------------------------------------
// Pass 1: global absmax of x
__global__ void k_absmax(const float* __restrict__ x, int n) {
    int n4 = n >> 2;
    float m = 0.0f;
    int stride = gridDim.x * blockDim.x;
    const float4* x4 = reinterpret_cast<const float4*>(x);
    for (int i = blockIdx.x * blockDim.x + threadIdx.x; i < n4; i += stride) {
        float4 v = x4[i];
        m = fmaxf(m, fmaxf(fmaxf(fabsf(v.x), fabsf(v.y)),
                           fmaxf(fabsf(v.z), fabsf(v.w))));
    }
    // tail (n not multiple of 4) — not hit for this dataset but safe
    for (int i = n4 * 4 + blockIdx.x * blockDim.x + threadIdx.x; i < n; i += stride)
        m = fmaxf(m, fabsf(x[i]));

    unsigned mb = __float_as_uint(m);            // m >= 0: bit order == value order
    mb = __reduce_max_sync(0xffffffffu, mb);
    __shared__ unsigned sm[THREADS / 32];
    if ((threadIdx.x & 31) == 0) sm[threadIdx.x >> 5] = mb;
    __syncthreads();
    if (threadIdx.x == 0) {
        unsigned v = 0;
        #pragma unroll
        for (int i = 0; i < THREADS / 32; i++) v = max(v, sm[i]);
        atomicMax(&g_absmax_bits, (int)v);
    }
}

__global__ void k_scale_in() {
    float amax = __int_as_float(g_absmax_bits);
    g_scale_in = fmaxf(amax / 127.0f, 1e-8f);
}

// ---------------------------------------------------------------------------
// Exact replica of reference sqrt_rounded_vec (LUT-based rounded int sqrt)
__device__ __forceinline__ float sqrt_rounded(int d) {
    // d in [1, 65535]
    int msb = 31 - __clz(d);                 // bit_length(d) - 1
    int k   = msb >> 1;
    int sh  = (7 - k) * 2;
    int dn  = d << sh;                       // normalize
    int addr = (dn >> 8) & 255;
    int v    = addr * 256 + 128;             // SQRT_LUT[addr] = isqrt(v)
    int mant = (int)sqrtf((float)v);
    if (mant * mant > v) mant--;
    if ((mant + 1) * (mant + 1) <= v) mant++;
    int qf = mant >> (7 - k);
    int boundary = qf * qf + qf;
    return (float)((d > boundary) ? qf + 1 : qf);
}

// ---------------------------------------------------------------------------
// Pass 2: per-row (N=4096, 256 threads, 4 float4/thread in registers):
//   int-domain Ex, Ex2 -> mu, inv_std; then per-row max|y| -> global ymax
__global__ void __launch_bounds__(THREADS)
k_rowstats(const float* __restrict__ x,
           const float* __restrict__ gamma,
           const float* __restrict__ beta,
           int N) {
    const int row = blockIdx.x;
    const int NIT = 4;                        // N / (THREADS*4) for N=4096
    const float4* xr = reinterpret_cast<const float4*>(x + (size_t)row * N);
    const float4* g4 = reinterpret_cast<const float4*>(gamma);
    const float4* b4 = reinterpret_cast<const float4*>(beta);
    const float s = g_scale_in;

    float4 xv[NIT];
    int isum = 0, isum2 = 0;
    #pragma unroll
    for (int j = 0; j < NIT; j++) {
        float4 v = xr[j * THREADS + threadIdx.x];
        xv[j] = v;
        #pragma unroll
        for (int c = 0; c < 4; c++) {
            float e = (&v.x)[c];
            float t = e / s;                              // IEEE div, matches ref
            float r = fminf(fmaxf(rintf(t), -127.0f), 127.0f);
            int q = (int)r;
            isum  += q;
            isum2 += q * q;                               // == LUT square, exact
        }
    }

    // block reduce (8 warps)
    __shared__ int sw[2][THREADS / 32];
    __shared__ float s_mu, s_is;
    int ws  = __reduce_add_sync(0xffffffffu, isum);
    int ws2 = __reduce_add_sync(0xffffffffu, isum2);
    if ((threadIdx.x & 31) == 0) {
        sw[0][threadIdx.x >> 5] = ws;
        sw[1][threadIdx.x >> 5] = ws2;
    }
    __syncthreads();
    if (threadIdx.x == 0) {
        int t = 0, t2 = 0;
        #pragma unroll
        for (int i = 0; i < THREADS / 32; i++) { t += sw[0][i]; t2 += sw[1][i]; }
        float Ex  = (float)t  * s;
        float Ex2 = (float)t2 * (s * s);
        float mu  = Ex / (float)N;
        float var = fmaxf(Ex2 / (float)N - mu * mu, 0.0f);
        float vi  = fminf(fmaxf(rintf(var), 1.0f), 65535.0f);
        float std_i = sqrt_rounded((int)vi);
        float inv = 1.0f / fmaxf(std_i, 1e-5f);
        g_mu[row] = mu;
        g_inv_std[row] = inv;
        s_mu = mu;
        s_is = inv;
    }
    __syncthreads();
    const float mu = s_mu, is = s_is;

    // per-row max |y| with y = ((x-mu)*inv_std)*gamma + beta
    float ymax = 0.0f;
    #pragma unroll
    for (int j = 0; j < NIT; j++) {
        float4 g = g4[j * THREADS + threadIdx.x];
        float4 b = b4[j * THREADS + threadIdx.x];
        #pragma unroll
        for (int c = 0; c < 4; c++) {
            float xn = ((&xv[j].x)[c] - mu) * is;
            float y  = xn * (&g.x)[c] + (&b.x)[c];
            ymax = fmaxf(ymax, fabsf(y));
        }
    }
    unsigned yb = __float_as_uint(ymax);
    yb = __reduce_max_sync(0xffffffffu, yb);
    __shared__ unsigned sy[THREADS / 32];
    if ((threadIdx.x & 31) == 0) sy[threadIdx.x >> 5] = yb;
    __syncthreads();
    if (threadIdx.x == 0) {
        unsigned v = 0;
        #pragma unroll
        for (int i = 0; i < THREADS / 32; i++) v = max(v, sy[i]);
        atomicMax(&g_ymax_bits, (int)v);
    }
}

__global__ void k_scale_out() {
    float ymax = __int_as_float(g_ymax_bits);
    g_scale_out = fmaxf(ymax / 127.0f, 1e-8f);
}

// ---------------------------------------------------------------------------
// Pass 3: recompute y, quantize with scale_out, write output
__global__ void __launch_bounds__(THREADS)
k_quant(const float* __restrict__ x,
        const float* __restrict__ gamma,
        const float* __restrict__ beta,
        float* __restrict__ out,
        int N) {
    const int row = blockIdx.x;
    const int NIT = 4;
    const float4* xr = reinterpret_cast<const float4*>(x + (size_t)row * N);
    const float4* g4 = reinterpret_cast<const float4*>(gamma);
    const float4* b4 = reinterpret_cast<const float4*>(beta);
    float4* orow = reinterpret_cast<float4*>(out + (size_t)row * N);

    const float mu = g_mu[row];
    const float is = g_inv_std[row];
    const float so = g_scale_out;

    #pragma unroll
    for (int j = 0; j < NIT; j++) {
        float4 v = xr[j * THREADS + threadIdx.x];
        float4 g = g4[j * THREADS + threadIdx.x];
        float4 b = b4[j * THREADS + threadIdx.x];
        float4 o;
        #pragma unroll
        for (int c = 0; c < 4; c++) {
            float xn = ((&v.x)[c] - mu) * is;
            float y  = xn * (&g.x)[c] + (&b.x)[c];
            float t  = y / so;                            // IEEE div, matches ref
            float r  = fminf(fmaxf(rintf(t), -127.0f), 127.0f);
            (&o.x)[c] = r * so;
        }
        orow[j * THREADS + threadIdx.x] = o;
    }
}

// ---------------------------------------------------------------------------
extern "C" void kernel_launch(void* const* d_in, const int* in_sizes, int n_in,
                              void* d_out, int out_size) {
    const float* x     = (const float*)d_in[0];
    const float* gamma = (const float*)d_in[1];
    const float* beta  = (const float*)d_in[2];
    float* out = (float*)d_out;

    const int N    = in_sizes[1];        // 4096
    const int n    = in_sizes[0];        // 4*2048*4096
    const int rows = n / N;              // 8192

    k_init<<<1, 1>>>();
    k_absmax<<<1184, THREADS>>>(x, n);
    k_scale_in<<<1, 1>>>();
    k_rowstats<<<rows, THREADS>>>(x, gamma, beta, N);
    k_scale_out<<<1, 1>>>();
    k_quant<<<rows, THREADS>>>(x, gamma, beta, out, N);
}

// round 2
// speedup vs baseline: 1.0971x; 1.0971x over previous
#include <cuda_runtime.h>

// ---------------------------------------------------------------------------
// ImprovedAILayerNorm: int8-quantized layernorm with LUT integer sqrt.
// 3 passes: global absmax -> per-row int moments + global |y| max -> quantize.
// R2: div->fmul(recip), 512thr/2xfloat4 (MLP_p1=2, kills L1tex-queue spread),
//     F2I.RN + int clamp, scale computation folded into consumers (4 launches).
// ---------------------------------------------------------------------------

#define T1 256          // absmax threads
#define T2 512          // rowstats/quant threads
#define MAX_ROWS 32768

__device__ int   g_absmax_bits;
__device__ int   g_ymax_bits;
__device__ float g_mu[MAX_ROWS];
__device__ float g_inv_std[MAX_ROWS];

__global__ void k_init() {
    g_absmax_bits = 0;
    g_ymax_bits   = 0;
}

// ---------------------------------------------------------------------------
// Pass 1: global absmax of x
__global__ void __launch_bounds__(T1)
k_absmax(const float* __restrict__ x, int n) {
    int n4 = n >> 2;
    const float4* x4 = reinterpret_cast<const float4*>(x);
    int stride = gridDim.x * blockDim.x;
    float m0 = 0.0f, m1 = 0.0f;
    for (int i = blockIdx.x * blockDim.x + threadIdx.x; i < n4; i += stride) {
        float4 v = x4[i];
        m0 = fmaxf(m0, fmaxf(fabsf(v.x), fabsf(v.y)));
        m1 = fmaxf(m1, fmaxf(fabsf(v.z), fabsf(v.w)));
    }
    for (int i = n4 * 4 + blockIdx.x * blockDim.x + threadIdx.x; i < n; i += stride)
        m0 = fmaxf(m0, fabsf(x[i]));
    float m = fmaxf(m0, m1);

    unsigned mb = __float_as_uint(m);                 // m >= 0
    mb = __reduce_max_sync(0xffffffffu, mb);
    __shared__ unsigned sm[T1 / 32];
    if ((threadIdx.x & 31) == 0) sm[threadIdx.x >> 5] = mb;
    __syncthreads();
    if (threadIdx.x == 0) {
        unsigned v = 0;
        #pragma unroll
        for (int i = 0; i < T1 / 32; i++) v = max(v, sm[i]);
        atomicMax(&g_absmax_bits, (int)v);
    }
}

// ---------------------------------------------------------------------------
// Exact replica of reference sqrt_rounded_vec (LUT-based rounded int sqrt)
__device__ __forceinline__ float sqrt_rounded(int d) {
    int msb = 31 - __clz(d);
    int k   = msb >> 1;
    int dn  = d << ((7 - k) * 2);
    int addr = (dn >> 8) & 255;
    int v    = addr * 256 + 128;                      // SQRT_LUT[addr] = isqrt(v)
    int mant = (int)sqrtf((float)v);
    if (mant * mant > v) mant--;
    if ((mant + 1) * (mant + 1) <= v) mant++;
    int qf = mant >> (7 - k);
    int boundary = qf * qf + qf;
    return (float)((d > boundary) ? qf + 1 : qf);
}

// ---------------------------------------------------------------------------
// Pass 2: per-row stats. 512 threads, 2 float4/thread held in registers.
__global__ void __launch_bounds__(T2)
k_rowstats(const float* __restrict__ x,
           const float* __restrict__ gamma,
           const float* __restrict__ beta,
           int N) {
    const int row = blockIdx.x;
    const int NIT = 2;                                 // N=4096 / (512*4)
    const float4* xr = reinterpret_cast<const float4*>(x + (size_t)row * N);
    const float4* g4 = reinterpret_cast<const float4*>(gamma);
    const float4* b4 = reinterpret_cast<const float4*>(beta);

    const float s     = fmaxf(__int_as_float(g_absmax_bits) / 127.0f, 1e-8f);
    const float inv_s = 1.0f / s;

    float4 xv[NIT];
    int isum = 0, isum2 = 0;
    #pragma unroll
    for (int j = 0; j < NIT; j++) {
        float4 v = xr[j * T2 + threadIdx.x];
        xv[j] = v;
        #pragma unroll
        for (int c = 0; c < 4; c++) {
            int q = __float2int_rn((&v.x)[c] * inv_s); // RN half-even == jnp.round
            q = max(-127, min(127, q));
            isum  += q;
            isum2 += q * q;
        }
    }

    __shared__ int sw[2][T2 / 32];
    __shared__ float s_mu, s_is;
    int ws  = __reduce_add_sync(0xffffffffu, isum);
    int ws2 = __reduce_add_sync(0xffffffffu, isum2);
    if ((threadIdx.x & 31) == 0) {
        sw[0][threadIdx.x >> 5] = ws;
        sw[1][threadIdx.x >> 5] = ws2;
    }
    __syncthreads();
    if (threadIdx.x == 0) {
        int t = 0, t2 = 0;
        #pragma unroll
        for (int i = 0; i < T2 / 32; i++) { t += sw[0][i]; t2 += sw[1][i]; }
        float Ex  = (float)t  * s;
        float Ex2 = (float)t2 * (s * s);
        float mu  = Ex / (float)N;
        float var = fmaxf(Ex2 / (float)N - mu * mu, 0.0f);
        float vi  = fminf(fmaxf(rintf(var), 1.0f), 65535.0f);
        float std_i = sqrt_rounded((int)vi);
        float inv = 1.0f / fmaxf(std_i, 1e-5f);
        g_mu[row] = mu;
        g_inv_std[row] = inv;
        s_mu = mu;
        s_is = inv;
    }
    __syncthreads();
    const float mu = s_mu, is = s_is;

    float ymax = 0.0f;
    #pragma unroll
    for (int j = 0; j < NIT; j++) {
        float4 g = g4[j * T2 + threadIdx.x];
        float4 b = b4[j * T2 + threadIdx.x];
        #pragma unroll
        for (int c = 0; c < 4; c++) {
            float xn = ((&xv[j].x)[c] - mu) * is;
            float y  = xn * (&g.x)[c] + (&b.x)[c];
            ymax = fmaxf(ymax, fabsf(y));
        }
    }
    unsigned yb = __float_as_uint(ymax);
    yb = __reduce_max_sync(0xffffffffu, yb);
    __shared__ unsigned sy[T2 / 32];
    if ((threadIdx.x & 31) == 0) sy[threadIdx.x >> 5] = yb;
    __syncthreads();
    if (threadIdx.x == 0) {
        unsigned v = 0;
        #pragma unroll
        for (int i = 0; i < T2 / 32; i++) v = max(v, sy[i]);
        atomicMax(&g_ymax_bits, (int)v);
    }
}

// ---------------------------------------------------------------------------
// Pass 3: recompute y, quantize, write. 512 threads, 2 float4/thread.
__global__ void __launch_bounds__(T2)
k_quant(const float* __restrict__ x,
        const float* __restrict__ gamma,
        const float* __restrict__ beta,
        float* __restrict__ out,
        int N) {
    const int row = blockIdx.x;
    const int NIT = 2;
    const float4* xr = reinterpret_cast<const float4*>(x + (size_t)row * N);
    const float4* g4 = reinterpret_cast<const float4*>(gamma);
    const float4* b4 = reinterpret_cast<const float4*>(beta);
    float4* orow = reinterpret_cast<float4*>(out + (size_t)row * N);

    const float mu = g_mu[row];
    const float is = g_inv_std[row];
    const float so     = fmaxf(__int_as_float(g_ymax_bits) / 127.0f, 1e-8f);
    const float inv_so = 1.0f / so;

    #pragma unroll
    for (int j = 0; j < NIT; j++) {
        float4 v = xr[j * T2 + threadIdx.x];
        float4 g = g4[j * T2 + threadIdx.x];
        float4 b = b4[j * T2 + threadIdx.x];
        float4 o;
        #pragma unroll
        for (int c = 0; c < 4; c++) {
            float xn = ((&v.x)[c] - mu) * is;
            float y  = xn * (&g.x)[c] + (&b.x)[c];
            int q = __float2int_rn(y * inv_so);
            q = max(-127, min(127, q));
            (&o.x)[c] = (float)q * so;
        }
        orow[j * T2 + threadIdx.x] = o;
    }
}

// ---------------------------------------------------------------------------
extern "C" void kernel_launch(void* const* d_in, const int* in_sizes, int n_in,
                              void* d_out, int out_size) {
    const float* x     = (const float*)d_in[0];
    const float* gamma = (const float*)d_in[1];
    const float* beta  = (const float*)d_in[2];
    float* out = (float*)d_out;

    const int N    = in_sizes[1];        // 4096
    const int n    = in_sizes[0];        // 4*2048*4096
    const int rows = n / N;              // 8192

    k_init<<<1, 1>>>();
    k_absmax<<<1184, T1>>>(x, n);
    k_rowstats<<<rows, T2>>>(x, gamma, beta, N);
    k_quant<<<rows, T2>>>(x, gamma, beta, out, N);
}

// round 3
// speedup vs baseline: 1.2513x; 1.1405x over previous
#include <cuda_runtime.h>

// ---------------------------------------------------------------------------
// ImprovedAILayerNorm: int8-quantized layernorm with LUT integer sqrt.
// R3: L2-serpentine pass ordering. x (128MiB) ~ L2 (126MB): pass1 ascending,
// pass2 DESCENDING (hits pass1's L2 residency), pass3 ascending (hits
// pass2's). Pass3 reads x with __ldcs and writes out with __stcs so the
// streaming output doesn't evict x.
// ---------------------------------------------------------------------------

#define T1 256          // absmax threads
#define T2 512          // rowstats/quant threads
#define MAX_ROWS 32768

__device__ int   g_absmax_bits;
__device__ int   g_ymax_bits;
__device__ float g_mu[MAX_ROWS];
__device__ float g_inv_std[MAX_ROWS];

__global__ void k_init() {
    g_absmax_bits = 0;
    g_ymax_bits   = 0;
}

// ---------------------------------------------------------------------------
// Pass 1: global absmax of x (ascending order, default caching: fill L2)
__global__ void __launch_bounds__(T1)
k_absmax(const float* __restrict__ x, int n) {
    int n4 = n >> 2;
    const float4* x4 = reinterpret_cast<const float4*>(x);
    int stride = gridDim.x * blockDim.x;
    float m0 = 0.0f, m1 = 0.0f;
    for (int i = blockIdx.x * blockDim.x + threadIdx.x; i < n4; i += stride) {
        float4 v = x4[i];
        m0 = fmaxf(m0, fmaxf(fabsf(v.x), fabsf(v.y)));
        m1 = fmaxf(m1, fmaxf(fabsf(v.z), fabsf(v.w)));
    }
    for (int i = n4 * 4 + blockIdx.x * blockDim.x + threadIdx.x; i < n; i += stride)
        m0 = fmaxf(m0, fabsf(x[i]));
    float m = fmaxf(m0, m1);

    unsigned mb = __float_as_uint(m);                 // m >= 0
    mb = __reduce_max_sync(0xffffffffu, mb);
    __shared__ unsigned sm[T1 / 32];
    if ((threadIdx.x & 31) == 0) sm[threadIdx.x >> 5] = mb;
    __syncthreads();
    if (threadIdx.x == 0) {
        unsigned v = 0;
        #pragma unroll
        for (int i = 0; i < T1 / 32; i++) v = max(v, sm[i]);
        atomicMax(&g_absmax_bits, (int)v);
    }
}

// ---------------------------------------------------------------------------
// Exact replica of reference sqrt_rounded_vec (LUT-based rounded int sqrt)
__device__ __forceinline__ float sqrt_rounded(int d) {
    int msb = 31 - __clz(d);
    int k   = msb >> 1;
    int dn  = d << ((7 - k) * 2);
    int addr = (dn >> 8) & 255;
    int v    = addr * 256 + 128;                      // SQRT_LUT[addr] = isqrt(v)
    int mant = (int)sqrtf((float)v);
    if (mant * mant > v) mant--;
    if ((mant + 1) * (mant + 1) <= v) mant++;
    int qf = mant >> (7 - k);
    int boundary = qf * qf + qf;
    return (float)((d > boundary) ? qf + 1 : qf);
}

// ---------------------------------------------------------------------------
// Pass 2: per-row stats. DESCENDING row order (rides pass-1 L2 residency).
__global__ void __launch_bounds__(T2)
k_rowstats(const float* __restrict__ x,
           const float* __restrict__ gamma,
           const float* __restrict__ beta,
           int N) {
    const int row = gridDim.x - 1 - blockIdx.x;        // descending traversal
    const int NIT = 2;                                 // N=4096 / (512*4)
    const float4* xr = reinterpret_cast<const float4*>(x + (size_t)row * N);
    const float4* g4 = reinterpret_cast<const float4*>(gamma);
    const float4* b4 = reinterpret_cast<const float4*>(beta);

    const float s     = fmaxf(__int_as_float(g_absmax_bits) / 127.0f, 1e-8f);
    const float inv_s = 1.0f / s;

    float4 xv[NIT];
    int isum = 0, isum2 = 0;
    #pragma unroll
    for (int j = 0; j < NIT; j++) {
        float4 v = xr[j * T2 + threadIdx.x];
        xv[j] = v;
        #pragma unroll
        for (int c = 0; c < 4; c++) {
            int q = __float2int_rn((&v.x)[c] * inv_s); // RN half-even == jnp.round
            q = max(-127, min(127, q));
            isum  += q;
            isum2 += q * q;
        }
    }

    __shared__ int sw[2][T2 / 32];
    __shared__ float s_mu, s_is;
    int ws  = __reduce_add_sync(0xffffffffu, isum);
    int ws2 = __reduce_add_sync(0xffffffffu, isum2);
    if ((threadIdx.x & 31) == 0) {
        sw[0][threadIdx.x >> 5] = ws;
        sw[1][threadIdx.x >> 5] = ws2;
    }
    __syncthreads();
    if (threadIdx.x == 0) {
        int t = 0, t2 = 0;
        #pragma unroll
        for (int i = 0; i < T2 / 32; i++) { t += sw[0][i]; t2 += sw[1][i]; }
        float Ex  = (float)t  * s;
        float Ex2 = (float)t2 * (s * s);
        float mu  = Ex / (float)N;
        float var = fmaxf(Ex2 / (float)N - mu * mu, 0.0f);
        float vi  = fminf(fmaxf(rintf(var), 1.0f), 65535.0f);
        float std_i = sqrt_rounded((int)vi);
        float inv = 1.0f / fmaxf(std_i, 1e-5f);
        g_mu[row] = mu;
        g_inv_std[row] = inv;
        s_mu = mu;
        s_is = inv;
    }
    __syncthreads();
    const float mu = s_mu, is = s_is;

    float ymax = 0.0f;
    #pragma unroll
    for (int j = 0; j < NIT; j++) {
        float4 g = g4[j * T2 + threadIdx.x];
        float4 b = b4[j * T2 + threadIdx.x];
        #pragma unroll
        for (int c = 0; c < 4; c++) {
            float xn = ((&xv[j].x)[c] - mu) * is;
            float y  = xn * (&g.x)[c] + (&b.x)[c];
            ymax = fmaxf(ymax, fabsf(y));
        }
    }
    unsigned yb = __float_as_uint(ymax);
    yb = __reduce_max_sync(0xffffffffu, yb);
    __shared__ unsigned sy[T2 / 32];
    if ((threadIdx.x & 31) == 0) sy[threadIdx.x >> 5] = yb;
    __syncthreads();
    if (threadIdx.x == 0) {
        unsigned v = 0;
        #pragma unroll
        for (int i = 0; i < T2 / 32; i++) v = max(v, sy[i]);
        atomicMax(&g_ymax_bits, (int)v);
    }
}

// ---------------------------------------------------------------------------
// Pass 3: ASCENDING row order (rides pass-2 L2 residency). x via __ldcs
// (evict-first: last use), out via __stcs (streaming: don't evict x).
__global__ void __launch_bounds__(T2)
k_quant(const float* __restrict__ x,
        const float* __restrict__ gamma,
        const float* __restrict__ beta,
        float* __restrict__ out,
        int N) {
    const int row = blockIdx.x;
    const int NIT = 2;
    const float4* xr = reinterpret_cast<const float4*>(x + (size_t)row * N);
    const float4* g4 = reinterpret_cast<const float4*>(gamma);
    const float4* b4 = reinterpret_cast<const float4*>(beta);
    float4* orow = reinterpret_cast<float4*>(out + (size_t)row * N);

    const float mu = g_mu[row];
    const float is = g_inv_std[row];
    const float so     = fmaxf(__int_as_float(g_ymax_bits) / 127.0f, 1e-8f);
    const float inv_so = 1.0f / so;

    #pragma unroll
    for (int j = 0; j < NIT; j++) {
        float4 v = __ldcs(&xr[j * T2 + threadIdx.x]);
        float4 g = g4[j * T2 + threadIdx.x];
        float4 b = b4[j * T2 + threadIdx.x];
        float4 o;
        #pragma unroll
        for (int c = 0; c < 4; c++) {
            float xn = ((&v.x)[c] - mu) * is;
            float y  = xn * (&g.x)[c] + (&b.x)[c];
            int q = __float2int_rn(y * inv_so);
            q = max(-127, min(127, q));
            (&o.x)[c] = (float)q * so;
        }
        __stcs(&orow[j * T2 + threadIdx.x], o);
    }
}

// ---------------------------------------------------------------------------
extern "C" void kernel_launch(void* const* d_in, const int* in_sizes, int n_in,
                              void* d_out, int out_size) {
    const float* x     = (const float*)d_in[0];
    const float* gamma = (const float*)d_in[1];
    const float* beta  = (const float*)d_in[2];
    float* out = (float*)d_out;

    const int N    = in_sizes[1];        // 4096
    const int n    = in_sizes[0];        // 4*2048*4096
    const int rows = n / N;              // 8192

    k_init<<<1, 1>>>();
    k_absmax<<<1184, T1>>>(x, n);
    k_rowstats<<<rows, T2>>>(x, gamma, beta, N);
    k_quant<<<rows, T2>>>(x, gamma, beta, out, N);
}